// round 11
// baseline (speedup 1.0000x reference)
#include <cuda_runtime.h>
#include <cstdint>

#define N_NODES 100000
#define N_EDGES 800000
#define C 128
#define FN 64000   // node split: node1 = [0,FN), node2 = [FN,N_NODES)

// Allocation-free scratch
__device__ __align__(16) float g_s[N_NODES];   // x_0[i] . att[:C]
__device__ __align__(16) float g_t[N_NODES];   // x_0[i] . att[C:]
__device__ int g_idx_is64;                     // 1 if indices are int64

// ---------------------------------------------------------------------------
// Node kernel (R4 per-warp shape, HBM roofline). BASE selects the node range;
// TRIG_START fires the PDL trigger at CTA start (node2) instead of end.
// End-trigger CTAs fence their stores first, so results are GPU-visible to
// any kernel whose launch is gated on the trigger.
// ---------------------------------------------------------------------------
template <bool TRIG_START, bool DETECT>
__global__ void __launch_bounds__(256) node_kernel(
    const float* __restrict__ x, const float* __restrict__ att,
    const unsigned int* __restrict__ src32, int base)
{
    if (TRIG_START)
        asm volatile("griddepcontrol.launch_dependents;" ::: "memory");

    if (DETECT && blockIdx.x == 0 && threadIdx.x == 0) {
        // int64 values < 2^31 have all-zero high words; 64 zero odd words
        // from random int32 ~ impossible.
        unsigned int acc = 0;
        #pragma unroll
        for (int i = 0; i < 64; ++i) acc |= src32[2 * i + 1];
        g_idx_is64 = (acc == 0u) ? 1 : 0;
    }

    const int lane = threadIdx.x & 31;
    const int warp = (blockIdx.x * blockDim.x + threadIdx.x) >> 5;
    const int n0 = base + warp * 4;              // grid sized exactly

    const float4 ws = reinterpret_cast<const float4*>(att)[lane];
    const float4 wt = reinterpret_cast<const float4*>(att + C)[lane];

    const float4* xr = reinterpret_cast<const float4*>(x + (size_t)n0 * C);
    const float4 x0 = xr[lane];
    const float4 x1 = xr[32 + lane];
    const float4 x2 = xr[64 + lane];
    const float4 x3 = xr[96 + lane];

    float s0 = x0.x*ws.x + x0.y*ws.y + x0.z*ws.z + x0.w*ws.w;
    float s1 = x1.x*ws.x + x1.y*ws.y + x1.z*ws.z + x1.w*ws.w;
    float s2 = x2.x*ws.x + x2.y*ws.y + x2.z*ws.z + x2.w*ws.w;
    float s3 = x3.x*ws.x + x3.y*ws.y + x3.z*ws.z + x3.w*ws.w;
    float t0 = x0.x*wt.x + x0.y*wt.y + x0.z*wt.z + x0.w*wt.w;
    float t1 = x1.x*wt.x + x1.y*wt.y + x1.z*wt.z + x1.w*wt.w;
    float t2 = x2.x*wt.x + x2.y*wt.y + x2.z*wt.z + x2.w*wt.w;
    float t3 = x3.x*wt.x + x3.y*wt.y + x3.z*wt.z + x3.w*wt.w;

    #pragma unroll
    for (int o = 16; o > 0; o >>= 1) {
        s0 += __shfl_xor_sync(0xffffffffu, s0, o);
        s1 += __shfl_xor_sync(0xffffffffu, s1, o);
        s2 += __shfl_xor_sync(0xffffffffu, s2, o);
        s3 += __shfl_xor_sync(0xffffffffu, s3, o);
        t0 += __shfl_xor_sync(0xffffffffu, t0, o);
        t1 += __shfl_xor_sync(0xffffffffu, t1, o);
        t2 += __shfl_xor_sync(0xffffffffu, t2, o);
        t3 += __shfl_xor_sync(0xffffffffu, t3, o);
    }

    if (lane == 0) {
        *reinterpret_cast<float4*>(g_s + n0) = make_float4(s0, s1, s2, s3);
        *reinterpret_cast<float4*>(g_t + n0) = make_float4(t0, t1, t2, t3);
    }

    if (!TRIG_START) {
        __threadfence();          // make g_s/g_t (and detect flag) GPU-visible
        __syncthreads();          // all CTA stores ordered before trigger
        asm volatile("griddepcontrol.launch_dependents;" ::: "memory");
    }
}

// ---------------------------------------------------------------------------
// Edge kernel, predicate-partitioned. TAKE_INSIDE=1 handles edges with both
// indices < FN (runs concurrently with node2 — touches only node1's tables);
// TAKE_INSIDE=0 handles the complement afterwards. Wavefront total conserved;
// the second index read is an L2 hit.
// ---------------------------------------------------------------------------
template <int TAKE_INSIDE>
__global__ void __launch_bounds__(256) edge_kernel_part(
    const void* __restrict__ src, const void* __restrict__ tgt,
    float* __restrict__ out)
{
    const int t = blockIdx.x * blockDim.x + threadIdx.x;
    if (t >= N_EDGES / 2) return;

    const int is64 = g_idx_is64;   // written + fenced by node1 before trigger

    int si0, si1, ti0, ti1;
    if (is64) {
        const longlong2 a = reinterpret_cast<const longlong2*>(src)[t];
        const longlong2 b = reinterpret_cast<const longlong2*>(tgt)[t];
        si0 = (int)a.x; si1 = (int)a.y;
        ti0 = (int)b.x; ti1 = (int)b.y;
    } else {
        const int2 a = reinterpret_cast<const int2*>(src)[t];
        const int2 b = reinterpret_cast<const int2*>(tgt)[t];
        si0 = a.x; si1 = a.y;
        ti0 = b.x; ti1 = b.y;
    }

    const bool in0 = (si0 < FN) && (ti0 < FN);
    const bool in1 = (si1 < FN) && (ti1 < FN);
    const bool do0 = (in0 == (TAKE_INSIDE != 0));
    const bool do1 = (in1 == (TAKE_INSIDE != 0));

    if (do0) out[2 * t]     = fmaxf(__ldg(g_s + si0) + __ldg(g_t + ti0), 0.0f);
    if (do1) out[2 * t + 1] = fmaxf(__ldg(g_s + si1) + __ldg(g_t + ti1), 0.0f);
}

extern "C" void kernel_launch(void* const* d_in, const int* in_sizes, int n_in,
                              void* d_out, int out_size) {
    const float* x_0 = (const float*)d_in[0];
    const void*  src = d_in[1];
    const void*  tgt = d_in[2];
    const float* att = (const float*)d_in[3];
    float* out = (float*)d_out;

    cudaLaunchAttribute pss[1];
    pss[0].id = cudaLaunchAttributeProgrammaticStreamSerialization;
    pss[0].val.programmaticStreamSerializationAllowed = 1;

    // 1) node1: nodes [0, FN). 16000 warps -> 2000 blocks. Detect + end-trigger.
    node_kernel<false, true><<<2000, 256>>>(x_0, att, (const unsigned int*)src, 0);

    // 2) node2: nodes [FN, N). 9000 warps -> 1125 blocks. PDL after node1's
    //    end-trigger (node1 results complete+visible); fires trigger at START
    //    so edgeA can launch immediately and overlap node2.
    {
        cudaLaunchConfig_t cfg = {};
        cfg.gridDim  = dim3(1125, 1, 1);
        cfg.blockDim = dim3(256, 1, 1);
        cfg.stream = 0;
        cfg.attrs = pss; cfg.numAttrs = 1;
        cudaLaunchKernelEx(&cfg, node_kernel<true, false>,
                           x_0, att, (const unsigned int*)src, (int)FN);
    }

    // 3) edgeA: inside-edges (both idx < FN). PDL after node2's start-trigger
    //    -> concurrent with node2. Safe: reads only node1's table entries.
    {
        cudaLaunchConfig_t cfg = {};
        cfg.gridDim  = dim3((N_EDGES / 2 + 255) / 256, 1, 1);   // 1563
        cfg.blockDim = dim3(256, 1, 1);
        cfg.stream = 0;
        cfg.attrs = pss; cfg.numAttrs = 1;
        cudaLaunchKernelEx(&cfg, edge_kernel_part<1>, src, tgt, out);
    }

    // 4) edgeB: complement edges. Plain launch -> waits node2 AND edgeA.
    edge_kernel_part<0><<<(N_EDGES / 2 + 255) / 256, 256>>>(src, tgt, out);
}

// round 12
// speedup vs baseline: 1.2183x; 1.2183x over previous
#include <cuda_runtime.h>
#include <cstdint>

#define N_NODES 100000
#define N_EDGES 800000
#define C 128

// Allocation-free scratch: per-node dot products (fp32, 16B-aligned)
__device__ __align__(16) float g_s[N_NODES];   // x_0[i] . att[:C]
__device__ __align__(16) float g_t[N_NODES];   // x_0[i] . att[C:]
__device__ int g_idx_is64;                     // 1 if indices are int64

// ---------------------------------------------------------------------------
// Node kernel (measured at HBM spec ~7.8 TB/s). Block 0 thread 0 runs the
// index dtype detect (int64 values < 2^31 have all-zero high words).
// PDL trigger on exit.
// ---------------------------------------------------------------------------
__global__ void __launch_bounds__(256) node_kernel(
    const float* __restrict__ x, const float* __restrict__ att,
    const unsigned int* __restrict__ src32)
{
    if (blockIdx.x == 0 && threadIdx.x == 0) {
        unsigned int acc = 0;
        #pragma unroll
        for (int i = 0; i < 64; ++i) acc |= src32[2 * i + 1];
        g_idx_is64 = (acc == 0u) ? 1 : 0;
    }

    const int lane = threadIdx.x & 31;
    const int warp = (blockIdx.x * blockDim.x + threadIdx.x) >> 5;  // 0..24999
    const int n0 = warp * 4;

    if (n0 < N_NODES) {
        const float4 ws = reinterpret_cast<const float4*>(att)[lane];
        const float4 wt = reinterpret_cast<const float4*>(att + C)[lane];

        const float4* xr = reinterpret_cast<const float4*>(x + (size_t)n0 * C);
        const float4 x0 = xr[lane];
        const float4 x1 = xr[32 + lane];
        const float4 x2 = xr[64 + lane];
        const float4 x3 = xr[96 + lane];

        float s0 = x0.x*ws.x + x0.y*ws.y + x0.z*ws.z + x0.w*ws.w;
        float s1 = x1.x*ws.x + x1.y*ws.y + x1.z*ws.z + x1.w*ws.w;
        float s2 = x2.x*ws.x + x2.y*ws.y + x2.z*ws.z + x2.w*ws.w;
        float s3 = x3.x*ws.x + x3.y*ws.y + x3.z*ws.z + x3.w*ws.w;
        float t0 = x0.x*wt.x + x0.y*wt.y + x0.z*wt.z + x0.w*wt.w;
        float t1 = x1.x*wt.x + x1.y*wt.y + x1.z*wt.z + x1.w*wt.w;
        float t2 = x2.x*wt.x + x2.y*wt.y + x2.z*wt.z + x2.w*wt.w;
        float t3 = x3.x*wt.x + x3.y*wt.y + x3.z*wt.z + x3.w*wt.w;

        #pragma unroll
        for (int o = 16; o > 0; o >>= 1) {
            s0 += __shfl_xor_sync(0xffffffffu, s0, o);
            s1 += __shfl_xor_sync(0xffffffffu, s1, o);
            s2 += __shfl_xor_sync(0xffffffffu, s2, o);
            s3 += __shfl_xor_sync(0xffffffffu, s3, o);
            t0 += __shfl_xor_sync(0xffffffffu, t0, o);
            t1 += __shfl_xor_sync(0xffffffffu, t1, o);
            t2 += __shfl_xor_sync(0xffffffffu, t2, o);
            t3 += __shfl_xor_sync(0xffffffffu, t3, o);
        }

        if (lane == 0) {
            *reinterpret_cast<float4*>(g_s + n0) = make_float4(s0, s1, s2, s3);
            *reinterpret_cast<float4*>(g_t + n0) = make_float4(t0, t1, t2, t3);
        }
    }

    asm volatile("griddepcontrol.launch_dependents;" ::: "memory");
}

// Streaming (evict-first) loads/stores: keep the 800KB s/t tables L2-resident
// by not letting single-use idx/out traffic claim residency.
__device__ __forceinline__ int2 ldcs_int2(const int2* p) {
    int2 v;
    asm("ld.global.cs.v2.s32 {%0, %1}, [%2];" : "=r"(v.x), "=r"(v.y) : "l"(p));
    return v;
}
__device__ __forceinline__ longlong2 ldcs_ll2(const longlong2* p) {
    longlong2 v;
    asm("ld.global.cs.v2.s64 {%0, %1}, [%2];" : "=l"(v.x), "=l"(v.y) : "l"(p));
    return v;
}
__device__ __forceinline__ void stcs_float2(float2* p, float2 v) {
    asm volatile("st.global.cs.v2.f32 [%0], {%1, %2};" :: "l"(p), "f"(v.x), "f"(v.y) : "memory");
}

// ---------------------------------------------------------------------------
// Edge kernel: best-measured shape (2 edges/thread, 400K threads, 1563
// blocks), PDL wait first, streaming policy on single-use traffic.
// ---------------------------------------------------------------------------
__global__ void __launch_bounds__(256) edge_kernel(
    const void* __restrict__ src, const void* __restrict__ tgt,
    float* __restrict__ out)
{
    asm volatile("griddepcontrol.wait;" ::: "memory");

    const int t = blockIdx.x * blockDim.x + threadIdx.x;
    if (t >= N_EDGES / 2) return;

    int si0, si1, ti0, ti1;
    if (g_idx_is64) {
        const longlong2 a = ldcs_ll2(reinterpret_cast<const longlong2*>(src) + t);
        const longlong2 b = ldcs_ll2(reinterpret_cast<const longlong2*>(tgt) + t);
        si0 = (int)a.x; si1 = (int)a.y;
        ti0 = (int)b.x; ti1 = (int)b.y;
    } else {
        const int2 a = ldcs_int2(reinterpret_cast<const int2*>(src) + t);
        const int2 b = ldcs_int2(reinterpret_cast<const int2*>(tgt) + t);
        si0 = a.x; si1 = a.y;
        ti0 = b.x; ti1 = b.y;
    }

    // 4 independent L2-resident gathers in flight
    const float s0 = __ldg(g_s + si0);
    const float s1 = __ldg(g_s + si1);
    const float v0 = __ldg(g_t + ti0);
    const float v1 = __ldg(g_t + ti1);

    float2 r;
    r.x = fmaxf(s0 + v0, 0.0f);
    r.y = fmaxf(s1 + v1, 0.0f);
    stcs_float2(reinterpret_cast<float2*>(out) + t, r);
}

extern "C" void kernel_launch(void* const* d_in, const int* in_sizes, int n_in,
                              void* d_out, int out_size) {
    const float* x_0 = (const float*)d_in[0];
    const void*  src = d_in[1];
    const void*  tgt = d_in[2];
    const float* att = (const float*)d_in[3];
    float* out = (float*)d_out;

    // Node pass: 25000 warps, 8 warps/block -> 3125 blocks (exact)
    node_kernel<<<3125, 256>>>(x_0, att, (const unsigned int*)src);

    // Edge pass: PDL into the node tail; best-measured grid shape.
    cudaLaunchConfig_t cfg = {};
    cfg.gridDim  = dim3((N_EDGES / 2 + 255) / 256, 1, 1);   // 1563
    cfg.blockDim = dim3(256, 1, 1);
    cfg.dynamicSmemBytes = 0;
    cfg.stream = 0;
    cudaLaunchAttribute attrs[1];
    attrs[0].id = cudaLaunchAttributeProgrammaticStreamSerialization;
    attrs[0].val.programmaticStreamSerializationAllowed = 1;
    cfg.attrs = attrs;
    cfg.numAttrs = 1;

    cudaLaunchKernelEx(&cfg, edge_kernel, src, tgt, out);
}